// round 10
// baseline (speedup 1.0000x reference)
#include <cuda_runtime.h>
#include <cuda_fp16.h>
#include <math.h>
#include <stdint.h>

// ---------------- problem constants (fixed by setup_inputs) ----------------
#define T_TOTAL 9792
#define EMBED   1024
#define HEADS   16
#define HDIM    64
#define NSEQ    12

// scratch (device globals -- allocation-free rule)
__device__ __half g_qh[T_TOTAL * EMBED];
__device__ __half g_kh[T_TOTAL * EMBED];
__device__ __half g_vh[T_TOTAL * EMBED];
__device__ __half g_attnh[T_TOTAL * EMBED];
__device__ __half g_hidh[T_TOTAL * EMBED];
__device__ __half g_qwh[EMBED * EMBED];
__device__ __half g_kwh[EMBED * EMBED];
__device__ __half g_vwh[EMBED * EMBED];
__device__ __half g_owh[EMBED * EMBED];

__constant__ int c_off13[NSEQ + 1] =
    {0,1024,1792,2688,3200,4224,4864,5888,6656,7168,8064,9088,9792};
// 128-row q-tile cumulative counts per sequence
__constant__ int c_qt_cum[NSEQ + 1] = {0,8,14,21,25,33,38,46,52,56,63,71,77};
#define NQT 77

// longest-job-first schedule over 128-row q-tiles (descending local tile index)
__constant__ short c_sched[NQT] = {
     7, 32, 45, 70,
     6, 20, 31, 44, 62, 69,
     5, 13, 19, 30, 43, 51, 61, 68, 76,
     4, 12, 18, 29, 37, 42, 50, 60, 67, 75,
     3, 11, 17, 24, 28, 36, 41, 49, 55, 59, 66, 74,
     2, 10, 16, 23, 27, 35, 40, 48, 54, 58, 65, 73,
     1,  9, 15, 22, 26, 34, 39, 47, 53, 57, 64, 72,
     0,  8, 14, 21, 25, 33, 38, 46, 52, 56, 63, 71
};

// ---------------- helpers ----------------
__device__ __forceinline__ unsigned smem_u32(const void* p) {
    return (unsigned)__cvta_generic_to_shared(p);
}
__device__ __forceinline__ unsigned h2_u(__half2 h) {
    return *reinterpret_cast<unsigned*>(&h);
}
__device__ __forceinline__ void cp_async16(unsigned saddr, const void* g) {
    asm volatile("cp.async.cg.shared.global [%0], [%1], 16;" :: "r"(saddr), "l"(g));
}
__device__ __forceinline__ void cp_async_commit() {
    asm volatile("cp.async.commit_group;");
}
template <int N>
__device__ __forceinline__ void cp_async_wait() {
    asm volatile("cp.async.wait_group %0;" :: "n"(N));
}
__device__ __forceinline__ void mma_f16(float* c, const unsigned* a, const unsigned* b) {
    asm volatile(
        "mma.sync.aligned.m16n8k16.row.col.f32.f16.f16.f32 "
        "{%0,%1,%2,%3}, {%4,%5,%6,%7}, {%8,%9}, {%0,%1,%2,%3};"
        : "+f"(c[0]), "+f"(c[1]), "+f"(c[2]), "+f"(c[3])
        : "r"(a[0]), "r"(a[1]), "r"(a[2]), "r"(a[3]), "r"(b[0]), "r"(b[1]));
}
__device__ __forceinline__ void ldsm_x4(unsigned& r0, unsigned& r1, unsigned& r2, unsigned& r3,
                                        unsigned saddr) {
    asm volatile("ldmatrix.sync.aligned.m8n8.x4.shared.b16 {%0,%1,%2,%3}, [%4];"
                 : "=r"(r0), "=r"(r1), "=r"(r2), "=r"(r3) : "r"(saddr));
}
__device__ __forceinline__ void ldsm_x4_t(unsigned& r0, unsigned& r1, unsigned& r2, unsigned& r3,
                                          unsigned saddr) {
    asm volatile("ldmatrix.sync.aligned.m8n8.x4.trans.shared.b16 {%0,%1,%2,%3}, [%4];"
                 : "=r"(r0), "=r"(r1), "=r"(r2), "=r"(r3) : "r"(saddr));
}

// ==================== fused fp32 -> fp16 pre-pass (hidden + 4 weights) ====================
#define H4 (T_TOTAL * EMBED / 4)
#define W4 (EMBED * EMBED / 4)

__global__ void cvt_all_kernel(const float4* __restrict__ hid,
                               const float4* __restrict__ qw, const float4* __restrict__ kw,
                               const float4* __restrict__ vw, const float4* __restrict__ ow,
                               __half2* dh, __half2* dqw, __half2* dkw, __half2* dvw, __half2* dow)
{
    int i = blockIdx.x * blockDim.x + threadIdx.x;
    const float4* src; __half2* dst; int off; float scale = 1.f;
    if (i < H4) {
        src = hid; dst = dh; off = i;
    } else {
        int j = i - H4;
        int seg = j >> 18;
        off = j & (W4 - 1);
        if (seg == 0)      { src = qw; dst = dqw; scale = 0.125f; }
        else if (seg == 1) { src = kw; dst = dkw; }
        else if (seg == 2) { src = vw; dst = dvw; }
        else if (seg == 3) { src = ow; dst = dow; }
        else return;
    }
    float4 v = src[off];
    dst[2 * off]     = __floats2half2_rn(v.x * scale, v.y * scale);
    dst[2 * off + 1] = __floats2half2_rn(v.z * scale, v.w * scale);
}

// ==================== fp16 tensor-core GEMM (3-stage, 1 sync/iter) ====================
#define GLD 40
#define G_SLOT (128 * GLD)
#define G_NST 3
#define G_SMEM_BYTES (G_NST * 2 * G_SLOT * 2)

extern __shared__ __half g_smh[];

__device__ __forceinline__ void gemm_issue_stage(
    const __half* A, const __half* W, int bm, int bn, int tid, int buf, int ko)
{
    __half* As = g_smh + buf * 2 * G_SLOT;
    __half* Bs = As + G_SLOT;
#pragma unroll
    for (int i = 0; i < 2; i++) {
        int idx = tid + i * 256;
        int row = idx >> 2, seg = idx & 3;
        int gm = bm + row; if (gm > T_TOTAL - 1) gm = T_TOTAL - 1;
        cp_async16(smem_u32(As + row * GLD + seg * 8), A + (size_t)gm * EMBED + ko + seg * 8);
        cp_async16(smem_u32(Bs + row * GLD + seg * 8), W + (size_t)(bn + row) * EMBED + ko + seg * 8);
    }
    cp_async_commit();
}

__global__ __launch_bounds__(256, 2)
void gemm_f16_kernel(const __half* __restrict__ A,
                     const __half* __restrict__ W0, const __half* __restrict__ W1,
                     const __half* __restrict__ W2,
                     const float* __restrict__ b0p, const float* __restrict__ b1p,
                     const float* __restrict__ b2p,
                     void* C0, void* C1, void* C2, int half_out)
{
    const int z = blockIdx.z;
    const __half* W = (z == 0) ? W0 : (z == 1) ? W1 : W2;
    const float* bias = (z == 0) ? b0p : (z == 1) ? b1p : b2p;
    void* Cout = (z == 0) ? C0 : (z == 1) ? C1 : C2;
    const float bscale = (half_out && z == 0) ? 0.125f : 1.0f;

    const int bm = blockIdx.y * 128;
    const int bn = blockIdx.x * 128;
    const int tid  = threadIdx.x;
    const int warp = tid >> 5;
    const int lane = tid & 31;
    const int wm = (warp >> 2) * 64;
    const int wn = (warp & 3) * 32;
    const int g = lane >> 2;
    const int c = lane & 3;

    const int a_r = ((lane >> 3) & 1) * 8 + (lane & 7);
    const int a_c = (lane >> 4) * 8;
    const int b_r = ((lane >> 4) << 3) + (lane & 7);
    const int b_c = ((lane >> 3) & 1) * 8;

    float acc[4][4][4];
#pragma unroll
    for (int mt = 0; mt < 4; mt++)
#pragma unroll
        for (int nt = 0; nt < 4; nt++)
#pragma unroll
            for (int r = 0; r < 4; r++) acc[mt][nt][r] = 0.f;

    gemm_issue_stage(A, W, bm, bn, tid, 0, 0);
    gemm_issue_stage(A, W, bm, bn, tid, 1, 32);

    int s = 0;
    for (int cc = 0; cc < 32; cc++) {
        cp_async_wait<1>();
        __syncthreads();

        const unsigned As = smem_u32(g_smh + s * 2 * G_SLOT);
        const unsigned Bs = As + G_SLOT * 2;
#pragma unroll
        for (int ks = 0; ks < 2; ks++) {
            const int k0 = ks * 16;
            unsigned af[4][4], bf[4][2];
#pragma unroll
            for (int mt = 0; mt < 4; mt++)
                ldsm_x4(af[mt][0], af[mt][1], af[mt][2], af[mt][3],
                        As + ((wm + mt * 16 + a_r) * GLD + k0 + a_c) * 2);
#pragma unroll
            for (int p = 0; p < 2; p++)
                ldsm_x4(bf[2*p][0], bf[2*p][1], bf[2*p+1][0], bf[2*p+1][1],
                        Bs + ((wn + p * 16 + b_r) * GLD + k0 + b_c) * 2);
#pragma unroll
            for (int mt = 0; mt < 4; mt++)
#pragma unroll
                for (int nt = 0; nt < 4; nt++)
                    mma_f16(acc[mt][nt], af[mt], bf[nt]);
        }

        if (cc + 2 < 32)
            gemm_issue_stage(A, W, bm, bn, tid, (s + 2 >= 3) ? s - 1 : s + 2, (cc + 2) * 32);
        else
            cp_async_commit();

        s = (s + 1 == 3) ? 0 : s + 1;
    }
    __syncthreads();

    const int c2 = c * 2;
    if (half_out) {
        __half* C = (__half*)Cout;
#pragma unroll
        for (int nt = 0; nt < 4; nt++) {
            int n = bn + wn + nt * 8 + c2;
            float2 bv = make_float2(0.f, 0.f);
            if (bias) { bv = *(const float2*)(bias + n); bv.x *= bscale; bv.y *= bscale; }
#pragma unroll
            for (int mt = 0; mt < 4; mt++) {
                int m = bm + wm + mt * 16 + g;
                if (m < T_TOTAL)
                    *(__half2*)(C + (size_t)m * EMBED + n) =
                        __floats2half2_rn(acc[mt][nt][0] + bv.x, acc[mt][nt][1] + bv.y);
                if (m + 8 < T_TOTAL)
                    *(__half2*)(C + (size_t)(m + 8) * EMBED + n) =
                        __floats2half2_rn(acc[mt][nt][2] + bv.x, acc[mt][nt][3] + bv.y);
            }
        }
    } else {
        float* C = (float*)Cout;
#pragma unroll
        for (int nt = 0; nt < 4; nt++) {
            int n = bn + wn + nt * 8 + c2;
            float2 bv = make_float2(0.f, 0.f);
            if (bias) bv = *(const float2*)(bias + n);
#pragma unroll
            for (int mt = 0; mt < 4; mt++) {
                int m = bm + wm + mt * 16 + g;
                if (m < T_TOTAL)
                    *(float2*)(C + (size_t)m * EMBED + n) =
                        make_float2(acc[mt][nt][0] + bv.x, acc[mt][nt][1] + bv.y);
                if (m + 8 < T_TOTAL)
                    *(float2*)(C + (size_t)(m + 8) * EMBED + n) =
                        make_float2(acc[mt][nt][2] + bv.x, acc[mt][nt][3] + bv.y);
            }
        }
    }
}

// ==================== RoPE (vectorized half2; fp32 math) ====================
__global__ void rope_kernel(const float* __restrict__ cosb, const float* __restrict__ sinb)
{
    int idx = blockIdx.x * blockDim.x + threadIdx.x;
    if (idx >= T_TOTAL * HEADS * 16) return;
    int d2 = idx & 15;
    int h  = (idx >> 4) & (HEADS - 1);
    int t  = idx >> 8;
    int d  = d2 * 2;

    float2 cv = *(const float2*)(cosb + t * HDIM + d);
    float2 sv = *(const float2*)(sinb + t * HDIM + d);

    size_t base = (size_t)t * EMBED + h * HDIM + d;
    {
        float2 a = __half22float2(*(__half2*)(g_qh + base));
        float2 b = __half22float2(*(__half2*)(g_qh + base + 32));
        *(__half2*)(g_qh + base)      = __floats2half2_rn(a.x * cv.x - b.x * sv.x,
                                                          a.y * cv.y - b.y * sv.y);
        *(__half2*)(g_qh + base + 32) = __floats2half2_rn(b.x * cv.x + a.x * sv.x,
                                                          b.y * cv.y + a.y * sv.y);
    }
    {
        float2 a = __half22float2(*(__half2*)(g_kh + base));
        float2 b = __half22float2(*(__half2*)(g_kh + base + 32));
        *(__half2*)(g_kh + base)      = __floats2half2_rn(a.x * cv.x - b.x * sv.x,
                                                          a.y * cv.y - b.y * sv.y);
        *(__half2*)(g_kh + base + 32) = __floats2half2_rn(b.x * cv.x + a.x * sv.x,
                                                          b.y * cv.y + a.y * sv.y);
    }
}

// ==================== Flash attention: 128-row q-tiles, 8 warps ====================
#define FLD 72
#define F_TILE (64 * FLD)                 // halves per K or V tile
#define F_STAGE (2 * F_TILE)              // K + V per stage
#define FQ_HALVES (128 * FLD)             // Q region
#define F_SMEM_BYTES ((FQ_HALVES + 2 * F_STAGE) * 2)

extern __shared__ __half f_smh[];

__device__ __forceinline__ void flash_issue_tile(int stage, const __half* kb, const __half* vb,
                                                 int tid)
{
    __half* Ks = f_smh + FQ_HALVES + stage * F_STAGE;
    __half* Vs = Ks + F_TILE;
#pragma unroll
    for (int i = 0; i < 2; i++) {
        int idx = tid + i * 256;            // 0..511
        int row = idx >> 3, seg = idx & 7;  // 64 rows x 8 chunks
        cp_async16(smem_u32(Ks + row * FLD + seg * 8), kb + (size_t)row * EMBED + seg * 8);
        cp_async16(smem_u32(Vs + row * FLD + seg * 8), vb + (size_t)row * EMBED + seg * 8);
    }
    cp_async_commit();
}

__global__ __launch_bounds__(256, 2)
void flash_mma_kernel()
{
    const int qt_global = c_sched[blockIdx.x];
    const int h = blockIdx.y;
    int b = 0;
    while (qt_global >= c_qt_cum[b + 1]) b++;
    const int t    = qt_global - c_qt_cum[b];
    const int off  = c_off13[b];
    const int slen = c_off13[b + 1] - off;
    const int t128 = t * 128;
    const int qrows = (slen - t128 < 128) ? (slen - t128) : 128;
    const int ktmax = (t128 + qrows - 1) >> 6;    // inclusive

    const int tid  = threadIdx.x;
    const int warp = tid >> 5;
    const int lane = tid & 31;
    const int g = lane >> 2;
    const int c = lane & 3;
    const int rb = warp * 16;                     // warp's q-row base (0..112)
    const int row_lo = t128 + rb;                 // within-seq global

    const int a_r = ((lane >> 3) & 1) * 8 + (lane & 7);
    const int a_c = (lane >> 4) * 8;
    const int b_r = ((lane >> 4) << 3) + (lane & 7);
    const int b_c = ((lane >> 3) & 1) * 8;

    const __half* kbase = g_kh + (size_t)off * EMBED + h * HDIM;
    const __half* vbase = g_vh + (size_t)off * EMBED + h * HDIM;

    flash_issue_tile(0, kbase, vbase, tid);

    // stage Q (pre-scaled by 1/8 via weight/bias scaling); clamp tail rows
    {
        __half* Qs = f_smh;
        const __half* qb = g_qh + (size_t)(off + t128) * EMBED + h * HDIM;
        int lr = tid >> 1, lc0 = (tid & 1) * 32;
        int sr = (lr < qrows) ? lr : (qrows - 1);
#pragma unroll
        for (int i = 0; i < 4; i++)
            *(uint4*)(Qs + lr * FLD + lc0 + 8 * i) =
                *(const uint4*)(qb + (size_t)sr * EMBED + lc0 + 8 * i);
    }
    __syncthreads();

    unsigned qf[4][4];
    {
        unsigned Qs = smem_u32(f_smh);
#pragma unroll
        for (int ks = 0; ks < 4; ks++)
            ldsm_x4(qf[ks][0], qf[ks][1], qf[ks][2], qf[ks][3],
                    Qs + ((rb + a_r) * FLD + ks * 16 + a_c) * 2);
    }

    float m0 = -1e30f, m1 = -1e30f, l0 = 0.f, l1 = 0.f;
    float oacc[8][4];
#pragma unroll
    for (int nt = 0; nt < 8; nt++)
#pragma unroll
        for (int r = 0; r < 4; r++) oacc[nt][r] = 0.f;

    for (int kt = 0; kt <= ktmax; kt++) {
        __syncthreads();
        if (kt < ktmax) {
            flash_issue_tile((kt + 1) & 1, kbase + (size_t)(kt + 1) * 64 * EMBED,
                             vbase + (size_t)(kt + 1) * 64 * EMBED, tid);
            cp_async_wait<1>();
        } else {
            cp_async_wait<0>();
        }
        __syncthreads();

        const int kb = kt * 64;
        if (kb > row_lo + 15) continue;   // whole warp masked (barriers already passed)

        const unsigned Ks = smem_u32(f_smh + FQ_HALVES + (kt & 1) * F_STAGE);
        const unsigned Vs = Ks + F_TILE * 2;

        float sacc[8][4];
#pragma unroll
        for (int nt = 0; nt < 8; nt++)
#pragma unroll
            for (int r = 0; r < 4; r++) sacc[nt][r] = 0.f;

#pragma unroll
        for (int ks = 0; ks < 4; ks++) {
#pragma unroll
            for (int p = 0; p < 4; p++) {
                unsigned bf[4];
                ldsm_x4(bf[0], bf[1], bf[2], bf[3],
                        Ks + ((p * 16 + b_r) * FLD + ks * 16 + b_c) * 2);
                mma_f16(sacc[2*p],     qf[ks], bf);
                mma_f16(sacc[2*p + 1], qf[ks], bf + 2);
            }
        }

        // causal mask (within-seq coords) on partial tiles
        if (kb + 63 > row_lo) {
            int r0 = row_lo + g, r1 = r0 + 8;
#pragma unroll
            for (int nt = 0; nt < 8; nt++) {
                int col = kb + nt * 8 + 2 * c;
                if (col     > r0) sacc[nt][0] = -1e30f;
                if (col + 1 > r0) sacc[nt][1] = -1e30f;
                if (col     > r1) sacc[nt][2] = -1e30f;
                if (col + 1 > r1) sacc[nt][3] = -1e30f;
            }
        }

        float mx0 = -1e30f, mx1 = -1e30f;
#pragma unroll
        for (int nt = 0; nt < 8; nt++) {
            mx0 = fmaxf(mx0, fmaxf(sacc[nt][0], sacc[nt][1]));
            mx1 = fmaxf(mx1, fmaxf(sacc[nt][2], sacc[nt][3]));
        }
        mx0 = fmaxf(mx0, __shfl_xor_sync(0xffffffffu, mx0, 1));
        mx0 = fmaxf(mx0, __shfl_xor_sync(0xffffffffu, mx0, 2));
        mx1 = fmaxf(mx1, __shfl_xor_sync(0xffffffffu, mx1, 1));
        mx1 = fmaxf(mx1, __shfl_xor_sync(0xffffffffu, mx1, 2));

        float mn0 = fmaxf(m0, mx0), mn1 = fmaxf(m1, mx1);
        float corr0 = __expf(m0 - mn0), corr1 = __expf(m1 - mn1);
        m0 = mn0; m1 = mn1;

        float ls0 = 0.f, ls1 = 0.f;
#pragma unroll
        for (int nt = 0; nt < 8; nt++) {
            sacc[nt][0] = __expf(sacc[nt][0] - mn0);
            sacc[nt][1] = __expf(sacc[nt][1] - mn0);
            sacc[nt][2] = __expf(sacc[nt][2] - mn1);
            sacc[nt][3] = __expf(sacc[nt][3] - mn1);
            ls0 += sacc[nt][0] + sacc[nt][1];
            ls1 += sacc[nt][2] + sacc[nt][3];
        }
        ls0 += __shfl_xor_sync(0xffffffffu, ls0, 1);
        ls0 += __shfl_xor_sync(0xffffffffu, ls0, 2);
        ls1 += __shfl_xor_sync(0xffffffffu, ls1, 1);
        ls1 += __shfl_xor_sync(0xffffffffu, ls1, 2);
        l0 = l0 * corr0 + ls0;
        l1 = l1 * corr1 + ls1;

#pragma unroll
        for (int nt = 0; nt < 8; nt++) {
            oacc[nt][0] *= corr0; oacc[nt][1] *= corr0;
            oacc[nt][2] *= corr1; oacc[nt][3] *= corr1;
        }

#pragma unroll
        for (int ks = 0; ks < 4; ks++) {
            unsigned pf[4];
            pf[0] = h2_u(__floats2half2_rn(sacc[2*ks][0],     sacc[2*ks][1]));
            pf[1] = h2_u(__floats2half2_rn(sacc[2*ks][2],     sacc[2*ks][3]));
            pf[2] = h2_u(__floats2half2_rn(sacc[2*ks + 1][0], sacc[2*ks + 1][1]));
            pf[3] = h2_u(__floats2half2_rn(sacc[2*ks + 1][2], sacc[2*ks + 1][3]));
#pragma unroll
            for (int p = 0; p < 4; p++) {
                unsigned bf[4];
                ldsm_x4_t(bf[0], bf[1], bf[2], bf[3],
                          Vs + ((ks * 16 + b_c + (lane & 7)) * FLD + p * 16 + (lane >> 4) * 8) * 2);
                mma_f16(oacc[2*p],     pf, bf);
                mma_f16(oacc[2*p + 1], pf, bf + 2);
            }
        }
    }

    // epilogue: normalize, store half (guard tail rows)
    if (rb + g < qrows) {
        float inv0 = 1.f / l0, inv1 = 1.f / l1;
        __half* ob = g_attnh + (size_t)(off + t128) * EMBED + h * HDIM;
        bool s1 = (rb + g + 8) < qrows;
#pragma unroll
        for (int nt = 0; nt < 8; nt++) {
            int col = nt * 8 + 2 * c;
            *(__half2*)(ob + (size_t)(rb + g) * EMBED + col) =
                __floats2half2_rn(oacc[nt][0] * inv0, oacc[nt][1] * inv0);
            if (s1)
                *(__half2*)(ob + (size_t)(rb + g + 8) * EMBED + col) =
                    __floats2half2_rn(oacc[nt][2] * inv1, oacc[nt][3] * inv1);
        }
    }
}

// ==================== launch ====================
extern "C" void kernel_launch(void* const* d_in, const int* in_sizes, int n_in,
                              void* d_out, int out_size)
{
    const float* hidden = (const float*)d_in[0];
    const float* cosb   = (const float*)d_in[1];
    const float* sinb   = (const float*)d_in[2];
    const float* q_w    = (const float*)d_in[3];
    const float* q_b    = (const float*)d_in[4];
    const float* k_w    = (const float*)d_in[5];
    const float* v_w    = (const float*)d_in[6];
    const float* v_b    = (const float*)d_in[7];
    const float* out_w  = (const float*)d_in[8];
    const float* out_b  = (const float*)d_in[9];
    float* out = (float*)d_out;

    __half *gq, *gk, *gv, *ga, *gh, *gqw, *gkw, *gvw, *gow;
    cudaGetSymbolAddress((void**)&gq,  g_qh);
    cudaGetSymbolAddress((void**)&gk,  g_kh);
    cudaGetSymbolAddress((void**)&gv,  g_vh);
    cudaGetSymbolAddress((void**)&ga,  g_attnh);
    cudaGetSymbolAddress((void**)&gh,  g_hidh);
    cudaGetSymbolAddress((void**)&gqw, g_qwh);
    cudaGetSymbolAddress((void**)&gkw, g_kwh);
    cudaGetSymbolAddress((void**)&gvw, g_vwh);
    cudaGetSymbolAddress((void**)&gow, g_owh);

    // fused fp32 -> fp16 pre-pass (q_w carries the 1/sqrt(64) scale)
    {
        int total = H4 + 4 * W4;
        cvt_all_kernel<<<(total + 255) / 256, 256>>>(
            (const float4*)hidden, (const float4*)q_w, (const float4*)k_w,
            (const float4*)v_w, (const float4*)out_w,
            (__half2*)gh, (__half2*)gqw, (__half2*)gkw, (__half2*)gvw, (__half2*)gow);
    }

    cudaFuncSetAttribute(gemm_f16_kernel, cudaFuncAttributeMaxDynamicSharedMemorySize, G_SMEM_BYTES);

    dim3 qkv_grid(EMBED / 128, (T_TOTAL + 127) / 128, 3);
    gemm_f16_kernel<<<qkv_grid, 256, G_SMEM_BYTES>>>(gh, gqw, gkw, gvw,
                                                     q_b, nullptr, v_b,
                                                     gq, gk, gv, 1);

    int rope_threads = T_TOTAL * HEADS * 16;
    rope_kernel<<<(rope_threads + 255) / 256, 256>>>(cosb, sinb);

    cudaFuncSetAttribute(flash_mma_kernel, cudaFuncAttributeMaxDynamicSharedMemorySize, F_SMEM_BYTES);
    flash_mma_kernel<<<dim3(NQT, HEADS), 256, F_SMEM_BYTES>>>();

    dim3 ogrid(EMBED / 128, (T_TOTAL + 127) / 128, 1);
    gemm_f16_kernel<<<ogrid, 256, G_SMEM_BYTES>>>(ga, gow, gow, gow,
                                                  out_b, nullptr, nullptr,
                                                  out, out, out, 0);
}